// round 9
// baseline (speedup 1.0000x reference)
#include <cuda_runtime.h>

// EMD / min-permutation matching on GB300.
//   B=32768, N=6, D=64.
//   cost[b] = (sum sq norms) - 2 * maxAssign(G),  G[n][m] = p_n . t_m
//   out[0] = sum_b cost[b]
//
// R9: 16 lanes/batch (4 dims/lane). All 12 loads per thread front-batched
// (R8's MLP) at ~100 regs (R6's 5 CTA/SM occupancy). Halved per-thread FMA.
// Tail: smem re-partition, 8 DP threads/CTA, rot-swizzled conflict-free reads.

#define BLOCK   128
#define SLOT    44    // 36 G + 1 sq + 7 pad; stride 44 -> STS.128 conflict-free

__global__ __launch_bounds__(BLOCK, 5)
void emd_kernel(const float* __restrict__ preds,
                const float* __restrict__ targets,
                float* __restrict__ out, int B)
{
    __shared__ float sh[BLOCK * SLOT];    // 22528 B

    const int t    = threadIdx.x;
    const int g    = blockIdx.x * BLOCK + t;
    const int bRaw = g >> 4;          // batch index
    const int j    = g & 15;          // lane within 16-thread group
    const int b = (bRaw < B) ? bRaw : (B - 1);   // clamp keeps lanes converged

    const float* pp = preds   + (size_t)b * 384 + 4 * j;
    const float* tt = targets + (size_t)b * 384 + 4 * j;

    // ---- 1) ALL 12 loads issued before any consumer (6 pred + 6 target rows)
    float4 p[6], q[6];
#pragma unroll
    for (int n = 0; n < 6; ++n) p[n] = *(const float4*)(pp + n * 64);
#pragma unroll
    for (int m = 0; m < 6; ++m) q[m] = *(const float4*)(tt + m * 64);

    // ---- 2) squared norms + partial Gram (4-dim slices)
    float sq = 0.0f;
#pragma unroll
    for (int n = 0; n < 6; ++n)
        sq += p[n].x*p[n].x + p[n].y*p[n].y + p[n].z*p[n].z + p[n].w*p[n].w;
#pragma unroll
    for (int m = 0; m < 6; ++m)
        sq += q[m].x*q[m].x + q[m].y*q[m].y + q[m].z*q[m].z + q[m].w*q[m].w;

    float G[36];
#pragma unroll
    for (int m = 0; m < 6; ++m)
#pragma unroll
        for (int n = 0; n < 6; ++n)
            G[n * 6 + m] = p[n].x*q[m].x + p[n].y*q[m].y
                         + p[n].z*q[m].z + p[n].w*q[m].w;

    // ---- 3) write partial (G, sq) to own slot; STS.128, conflict-free
    {
        float* slot = &sh[t * SLOT];
#pragma unroll
        for (int i = 0; i < 9; ++i)
            *(float4*)&slot[4 * i] = make_float4(G[4*i], G[4*i+1], G[4*i+2], G[4*i+3]);
        slot[36] = sq;
    }
    __syncthreads();

    // ---- 4) one thread per batch: sum 16 partials, run DP
    float cost = 0.0f;
    if (t < BLOCK / 16) {                        // 8 batches per CTA
        const int bOut = blockIdx.x * (BLOCK / 16) + t;
        float A[37];
#pragma unroll
        for (int i = 0; i < 37; ++i) A[i] = 0.0f;

#pragma unroll
        for (int l = 0; l < 16; ++l) {
            const int rot = (l + t) & 15;                // de-conflict rotation
            const float* slot = &sh[(t * 16 + rot) * SLOT];
#pragma unroll
            for (int e = 0; e < 9; ++e) {
                float4 v = *(const float4*)&slot[4 * e];
                A[4*e]   += v.x;  A[4*e+1] += v.y;
                A[4*e+2] += v.z;  A[4*e+3] += v.w;
            }
            A[36] += slot[36];
        }

        if (bOut < B) {
            float dp[64];
            dp[0] = 0.0f;
#pragma unroll
            for (int k = 1; k <= 6; ++k) {
                const int r = k - 1;
#pragma unroll
                for (int S = 1; S < 64; ++S) {
                    if (__popc((unsigned)S) == k) {
                        float best = -3.0e38f;
#pragma unroll
                        for (int m = 0; m < 6; ++m)
                            if (S & (1 << m))
                                best = fmaxf(best, dp[S ^ (1 << m)] + A[r * 6 + m]);
                        dp[S] = best;
                    }
                }
            }
            cost = A[36] - 2.0f * dp[63];
        }
    }

    // ---- 5) reduce the 8 costs (first warp) and atomicAdd once
    if (t < 32) {
#pragma unroll
        for (int o = 4; o > 0; o >>= 1)
            cost += __shfl_down_sync(0xffffffffu, cost, o);
        if (t == 0) atomicAdd(out, cost);
    }
}

extern "C" void kernel_launch(void* const* d_in, const int* in_sizes, int n_in,
                              void* d_out, int out_size)
{
    const float* preds   = (const float*)d_in[0];
    const float* targets = (const float*)d_in[1];
    const int B = in_sizes[0] / 384;   // 6 * 64 floats per batch

    cudaMemsetAsync(d_out, 0, sizeof(float));
    const long long threads = (long long)B * 16;
    const int grid = (int)((threads + BLOCK - 1) / BLOCK);
    emd_kernel<<<grid, BLOCK>>>(preds, targets, (float*)d_out, B);
}

// round 10
// speedup vs baseline: 1.3028x; 1.3028x over previous
#include <cuda_runtime.h>

// EMD / min-permutation matching on GB300 — TMA bulk double-buffered pipeline.
//   B=32768, N=6, D=64.
//   cost[b] = (sum sq norms) - 2 * maxAssign(G),  G[n][m] = p_n . t_m
//   out[0] = sum_b cost[b]
//
// R10: persistent CTAs (2/SM), each tile = 16 batches. Loads via two
// cp.async.bulk 24.6KB contiguous copies per tile into a 2-stage SMEM ring
// (async proxy; bypasses per-lane LDG queues). Compute = R6 shape from SMEM:
// 8 lanes/batch, p slice in regs, q streamed LDS.128 conflict-free.
// Partials reuse the consumed pred-slice region; DP one-thread-per-batch.

#define BLOCK   128
#define TILE_B  16
#define TILE_FL (TILE_B * 384 * 2)     // 12288 floats per stage
#define HALF_B  (TILE_B * 384 * 4)     // 24576 bytes per tensor per tile
#define STAGE_B (2 * HALF_B)           // 49152 bytes per stage
#define SLOTS   44                     // partial stride: 44%32==12 -> conflict-free

__device__ __forceinline__ unsigned sa(const void* p) {
    return (unsigned)__cvta_generic_to_shared(p);
}
__device__ __forceinline__ void mbar_init(unsigned a, unsigned cnt) {
    asm volatile("mbarrier.init.shared.b64 [%0], %1;" :: "r"(a), "r"(cnt) : "memory");
}
__device__ __forceinline__ void mbar_expect_tx(unsigned a, unsigned bytes) {
    asm volatile("mbarrier.arrive.expect_tx.shared.b64 _, [%0], %1;"
                 :: "r"(a), "r"(bytes) : "memory");
}
__device__ __forceinline__ void mbar_wait(unsigned a, unsigned parity) {
    asm volatile(
        "{\n\t.reg .pred P;\n"
        "W%=:\n\t"
        "mbarrier.try_wait.parity.acquire.cta.shared::cta.b64 P, [%0], %1, 0x989680;\n\t"
        "@!P bra W%=;\n\t}"
        :: "r"(a), "r"(parity) : "memory");
}
__device__ __forceinline__ void bulk_g2s(unsigned dst, const void* src,
                                         unsigned bytes, unsigned bar) {
    asm volatile(
        "cp.async.bulk.shared::cluster.global.mbarrier::complete_tx::bytes "
        "[%0], [%1], %2, [%3];"
        :: "r"(dst), "l"(src), "r"(bytes), "r"(bar) : "memory");
}
__device__ __forceinline__ void fence_proxy() {
    asm volatile("fence.proxy.async.shared::cta;" ::: "memory");
}

__global__ void __launch_bounds__(BLOCK)
emd_kernel(const float* __restrict__ preds,
           const float* __restrict__ targets,
           float* __restrict__ out, int B, int ntiles)
{
    extern __shared__ float sbuf[];          // 2 * TILE_FL floats (96 KB)
    __shared__ unsigned long long mbar[2];

    const int t  = threadIdx.x;
    const int bb = t >> 3;                   // batch within tile (0..15)
    const int j  = t & 7;                    // lane within batch group

    const unsigned bar0 = sa(&mbar[0]);
    const unsigned bar1 = sa(&mbar[1]);
    const unsigned stg0 = sa(&sbuf[0]);

    // ---- init barriers + prologue: issue tiles k=0,1 into stages 0,1
    if (t == 0) {
        mbar_init(bar0, 1);
        mbar_init(bar1, 1);
        fence_proxy();
#pragma unroll
        for (int k = 0; k < 2; ++k) {
            int tile = blockIdx.x + k * gridDim.x;
            if (tile < ntiles) {
                unsigned nb    = (unsigned)min(TILE_B, B - tile * TILE_B);
                unsigned bytes = nb * 1536u;
                unsigned bar   = k ? bar1 : bar0;
                unsigned dst   = stg0 + (unsigned)k * STAGE_B;
                mbar_expect_tx(bar, 2u * bytes);
                bulk_g2s(dst,          preds   + (size_t)tile * 6144, bytes, bar);
                bulk_g2s(dst + HALF_B, targets + (size_t)tile * 6144, bytes, bar);
            }
        }
    }
    __syncthreads();

    float cost = 0.0f;
    int k = 0;
    for (int tile = blockIdx.x; tile < ntiles; tile += gridDim.x, ++k) {
        const int s = k & 1;
        mbar_wait(s ? bar1 : bar0, (unsigned)((k >> 1) & 1));

        float* stg = sbuf + s * TILE_FL;
        const float* myp = stg + bb * 384 + 4 * j;
        const float* myq = stg + TILE_B * 384 + bb * 384 + 4 * j;

        // ---- p slice into regs (LDS.128, conflict-free: 128B rows per phase)
        float4 pa[6], pc[6];
#pragma unroll
        for (int n = 0; n < 6; ++n) {
            pa[n] = *(const float4*)(myp + n * 64);
            pc[n] = *(const float4*)(myp + n * 64 + 32);
        }

        float sq = 0.0f;
#pragma unroll
        for (int n = 0; n < 6; ++n) {
            sq += pa[n].x*pa[n].x + pa[n].y*pa[n].y + pa[n].z*pa[n].z + pa[n].w*pa[n].w;
            sq += pc[n].x*pc[n].x + pc[n].y*pc[n].y + pc[n].z*pc[n].z + pc[n].w*pc[n].w;
        }

        float G[36];
#pragma unroll
        for (int m = 0; m < 6; ++m) {
            float4 qa = *(const float4*)(myq + m * 64);
            float4 qc = *(const float4*)(myq + m * 64 + 32);
            sq += qa.x*qa.x + qa.y*qa.y + qa.z*qa.z + qa.w*qa.w;
            sq += qc.x*qc.x + qc.y*qc.y + qc.z*qc.z + qc.w*qc.w;
#pragma unroll
            for (int n = 0; n < 6; ++n) {
                G[n * 6 + m] = pa[n].x*qa.x + pa[n].y*qa.y + pa[n].z*qa.z + pa[n].w*qa.w
                             + pc[n].x*qc.x + pc[n].y*qc.y + pc[n].z*qc.z + pc[n].w*qc.w;
            }
        }

        // ---- write partial (G, sq) into own pred-slice region (consumed)
        __syncwarp();                        // all p reads done before overwrite
        {
            float* slot = stg + bb * 384 + j * SLOTS;
#pragma unroll
            for (int e = 0; e < 9; ++e)
                *(float4*)&slot[4 * e] =
                    make_float4(G[4*e], G[4*e+1], G[4*e+2], G[4*e+3]);
            slot[36] = sq;
        }
        __syncthreads();

        // ---- one thread per batch: sum 8 partials, run subset DP
        if (t < TILE_B) {
            const int bOut = tile * TILE_B + t;
            float A[37];
#pragma unroll
            for (int i = 0; i < 37; ++i) A[i] = 0.0f;
#pragma unroll
            for (int l = 0; l < 8; ++l) {
                const int rot = (l + t) & 7;
                const float* slot = stg + t * 384 + rot * SLOTS;
#pragma unroll
                for (int e = 0; e < 9; ++e) {
                    float4 v = *(const float4*)&slot[4 * e];
                    A[4*e]   += v.x;  A[4*e+1] += v.y;
                    A[4*e+2] += v.z;  A[4*e+3] += v.w;
                }
                A[36] += slot[36];
            }
            if (bOut < B) {
                float dp[64];
                dp[0] = 0.0f;
#pragma unroll
                for (int kk = 1; kk <= 6; ++kk) {
                    const int r = kk - 1;
#pragma unroll
                    for (int S = 1; S < 64; ++S) {
                        if (__popc((unsigned)S) == kk) {
                            float best = -3.0e38f;
#pragma unroll
                            for (int m = 0; m < 6; ++m)
                                if (S & (1 << m))
                                    best = fmaxf(best, dp[S ^ (1 << m)] + A[r * 6 + m]);
                            dp[S] = best;
                        }
                    }
                }
                cost += A[36] - 2.0f * dp[63];
            }
        }
        __syncthreads();                     // partial reads done before reissue

        // ---- reissue this stage for tile k+2
        if (t == 0) {
            int nt = tile + 2 * gridDim.x;
            if (nt < ntiles) {
                unsigned nb    = (unsigned)min(TILE_B, B - nt * TILE_B);
                unsigned bytes = nb * 1536u;
                unsigned bar   = s ? bar1 : bar0;
                unsigned dst   = stg0 + (unsigned)s * STAGE_B;
                fence_proxy();               // order generic reads before async writes
                mbar_expect_tx(bar, 2u * bytes);
                bulk_g2s(dst,          preds   + (size_t)nt * 6144, bytes, bar);
                bulk_g2s(dst + HALF_B, targets + (size_t)nt * 6144, bytes, bar);
            }
        }
    }

    // ---- one atomicAdd per CTA
    if (t < 32) {
#pragma unroll
        for (int o = 8; o > 0; o >>= 1)
            cost += __shfl_down_sync(0xffffffffu, cost, o);
        if (t == 0) atomicAdd(out, cost);
    }
}

extern "C" void kernel_launch(void* const* d_in, const int* in_sizes, int n_in,
                              void* d_out, int out_size)
{
    const float* preds   = (const float*)d_in[0];
    const float* targets = (const float*)d_in[1];
    const int B = in_sizes[0] / 384;           // 6 * 64 floats per batch
    const int ntiles = (B + TILE_B - 1) / TILE_B;

    const int smem = 2 * STAGE_B;              // 98304 B dynamic
    cudaFuncSetAttribute(emd_kernel,
                         cudaFuncAttributeMaxDynamicSharedMemorySize, smem);

    cudaMemsetAsync(d_out, 0, sizeof(float));
    int grid = 2 * 148;                        // persistent: 2 CTAs per SM
    if (grid > ntiles) grid = ntiles;
    emd_kernel<<<grid, BLOCK, smem>>>(preds, targets, (float*)d_out, B, ntiles);
}

// round 11
// speedup vs baseline: 1.3257x; 1.0176x over previous
#include <cuda_runtime.h>

// EMD / min-permutation matching on GB300.
//   B=32768, N=6, D=64.
//   cost[b] = (sum sq norms) - 2 * maxAssign(G),  G[n][m] = p_n . t_m
//   out[0] = sum_b cost[b]
//
// R11 = R8 (all 24 loads front-batched, smem re-partition tail) but at
// __launch_bounds__(128,4): R8 compiled to 114 regs, which fits a 128-reg
// cap, so we get 4 CTA/SM (16 warps) with the identical schedule.
// Tail trimmed: accumulator seeded from first partial slot.

#define BLOCK   128
#define SLOT    44    // 36 G + 1 sq + 7 pad; 44 % 32 == 12 -> STS.128 conflict-free

__global__ __launch_bounds__(BLOCK, 4)
void emd_kernel(const float* __restrict__ preds,
                const float* __restrict__ targets,
                float* __restrict__ out, int B)
{
    __shared__ float sh[BLOCK * SLOT];    // 22528 B

    const int t    = threadIdx.x;
    const int g    = blockIdx.x * BLOCK + t;
    const int bRaw = g >> 3;          // batch index
    const int j    = g & 7;           // lane within 8-thread group
    const int b = (bRaw < B) ? bRaw : (B - 1);   // clamp keeps lanes converged

    const float* pp = preds   + (size_t)b * 384 + 4 * j;
    const float* tt = targets + (size_t)b * 384 + 4 * j;

    // ---- 1) ALL 24 loads issued before any consumer (max MLP)
    float4 pa[6], pc[6], qa[6], qc[6];
#pragma unroll
    for (int n = 0; n < 6; ++n) {
        pa[n] = *(const float4*)(pp + n * 64);
        pc[n] = *(const float4*)(pp + n * 64 + 32);
    }
#pragma unroll
    for (int m = 0; m < 6; ++m) {
        qa[m] = *(const float4*)(tt + m * 64);
        qc[m] = *(const float4*)(tt + m * 64 + 32);
    }

    // ---- 2) squared norms + partial Gram, register-resident
    float sq = 0.0f;
#pragma unroll
    for (int n = 0; n < 6; ++n) {
        sq += pa[n].x*pa[n].x + pa[n].y*pa[n].y + pa[n].z*pa[n].z + pa[n].w*pa[n].w;
        sq += pc[n].x*pc[n].x + pc[n].y*pc[n].y + pc[n].z*pc[n].z + pc[n].w*pc[n].w;
    }
#pragma unroll
    for (int m = 0; m < 6; ++m) {
        sq += qa[m].x*qa[m].x + qa[m].y*qa[m].y + qa[m].z*qa[m].z + qa[m].w*qa[m].w;
        sq += qc[m].x*qc[m].x + qc[m].y*qc[m].y + qc[m].z*qc[m].z + qc[m].w*qc[m].w;
    }

    float G[36];
#pragma unroll
    for (int m = 0; m < 6; ++m) {
#pragma unroll
        for (int n = 0; n < 6; ++n) {
            G[n * 6 + m] = pa[n].x*qa[m].x + pa[n].y*qa[m].y
                         + pa[n].z*qa[m].z + pa[n].w*qa[m].w
                         + pc[n].x*qc[m].x + pc[n].y*qc[m].y
                         + pc[n].z*qc[m].z + pc[n].w*qc[m].w;
        }
    }

    // ---- 3) write partial (G, sq) to own slot; STS.128, conflict-free
    {
        float* slot = &sh[t * SLOT];
#pragma unroll
        for (int i = 0; i < 9; ++i)
            *(float4*)&slot[4 * i] = make_float4(G[4*i], G[4*i+1], G[4*i+2], G[4*i+3]);
        slot[36] = sq;
    }
    __syncthreads();

    // ---- 4) one thread per batch: sum 8 partials, run DP
    float cost = 0.0f;
    if (t < BLOCK / 8) {                         // 16 batches per CTA
        const int bOut = blockIdx.x * (BLOCK / 8) + t;
        float A[37];

        // seed from first (rotated) slot, then accumulate remaining 7
        {
            const int rot0 = t & 7;
            const float* slot = &sh[(t * 8 + rot0) * SLOT];
#pragma unroll
            for (int e = 0; e < 9; ++e) {
                float4 v = *(const float4*)&slot[4 * e];
                A[4*e]   = v.x;  A[4*e+1] = v.y;
                A[4*e+2] = v.z;  A[4*e+3] = v.w;
            }
            A[36] = slot[36];
        }
#pragma unroll
        for (int l = 1; l < 8; ++l) {
            const int rot = (l + t) & 7;                 // de-conflict rotation
            const float* slot = &sh[(t * 8 + rot) * SLOT];
#pragma unroll
            for (int e = 0; e < 9; ++e) {
                float4 v = *(const float4*)&slot[4 * e];
                A[4*e]   += v.x;  A[4*e+1] += v.y;
                A[4*e+2] += v.z;  A[4*e+3] += v.w;
            }
            A[36] += slot[36];
        }

        if (bOut < B) {
            float dp[64];
            dp[0] = 0.0f;
#pragma unroll
            for (int k = 1; k <= 6; ++k) {
                const int r = k - 1;
#pragma unroll
                for (int S = 1; S < 64; ++S) {
                    if (__popc((unsigned)S) == k) {
                        float best = -3.0e38f;
#pragma unroll
                        for (int m = 0; m < 6; ++m)
                            if (S & (1 << m))
                                best = fmaxf(best, dp[S ^ (1 << m)] + A[r * 6 + m]);
                        dp[S] = best;
                    }
                }
            }
            cost = A[36] - 2.0f * dp[63];
        }
    }

    // ---- 5) reduce the 16 costs (first warp) and atomicAdd once
    if (t < 32) {
#pragma unroll
        for (int o = 8; o > 0; o >>= 1)
            cost += __shfl_down_sync(0xffffffffu, cost, o);
        if (t == 0) atomicAdd(out, cost);
    }
}

extern "C" void kernel_launch(void* const* d_in, const int* in_sizes, int n_in,
                              void* d_out, int out_size)
{
    const float* preds   = (const float*)d_in[0];
    const float* targets = (const float*)d_in[1];
    const int B = in_sizes[0] / 384;   // 6 * 64 floats per batch

    cudaMemsetAsync(d_out, 0, sizeof(float));
    const long long threads = (long long)B * 8;
    const int grid = (int)((threads + BLOCK - 1) / BLOCK);
    emd_kernel<<<grid, BLOCK>>>(preds, targets, (float*)d_out, B);
}